// round 10
// baseline (speedup 1.0000x reference)
#include <cuda_runtime.h>
#include <cuda_bf16.h>
#include <stdint.h>
#include <math.h>

// Problem constants
#define CIN    64
#define HWD    56
#define LL     3136
#define COUT   128
#define MM     100352
#define DD     576
#define BM     128
#define BK     64
#define NCHUNK 9
#define THREADS 384          // warps 0-7 consumers, 8-11 producers
#define INV_PI 0.3183098861837907f
#define EPS_F  4e-4f         // boundary band (> hard bound ~2e-5 on |f err|)

// 2-way bf16 split of W, [COUT][DD] (k-contiguous = exactly what ldmatrix B wants)
__device__ __nv_bfloat16 g_Wh[COUT*DD];
__device__ __nv_bfloat16 g_Wm[COUT*DD];

__global__ void split_w_kernel(const float* __restrict__ W) {
    int i = blockIdx.x * 256 + threadIdx.x;
    if (i < COUT * DD) {
        float v = W[i];
        __nv_bfloat16 h = __float2bfloat16(v);
        float r1 = v - __bfloat162float(h);
        g_Wh[i] = h;
        g_Wm[i] = __float2bfloat16(r1);
    }
}

// ---------------- PTX helpers ----------------
__device__ __forceinline__ uint32_t smem_u32(const void* p) {
    uint32_t a;
    asm("{ .reg .u64 t; cvta.to.shared.u64 t, %1; cvt.u32.u64 %0, t; }" : "=r"(a) : "l"(p));
    return a;
}
#define MBAR_INIT(a, n) asm volatile("mbarrier.init.shared.b64 [%0], %1;" :: "r"(a), "r"(n) : "memory")
#define MBAR_ARRIVE(a)  asm volatile("mbarrier.arrive.shared.b64 _, [%0];" :: "r"(a) : "memory")
#define MBAR_WAIT(a, ph) do { \
    uint32_t _m = (a); uint32_t _p = (ph); uint32_t _d; \
    asm volatile("{\n\t.reg .pred p;\n\t" \
        "mbarrier.try_wait.parity.acquire.cta.shared::cta.b64 p, [%1], %2;\n\t" \
        "selp.b32 %0, 1, 0, p;\n\t}" : "=r"(_d) : "r"(_m), "r"(_p) : "memory"); \
    if (!_d) { \
        asm volatile("{\n\t.reg .pred P1;\n\t" \
            "WL_%=:\n\t" \
            "mbarrier.try_wait.parity.acquire.cta.shared::cta.b64 P1, [%0], %1, 0x989680;\n\t" \
            "@P1 bra.uni WD_%=;\n\t" \
            "bra.uni WL_%=;\n\t" \
            "WD_%=:\n\t}" :: "r"(_m), "r"(_p) : "memory"); \
    } } while (0)

#define STS128(a, v) asm volatile("st.shared.v4.b32 [%0], {%1,%2,%3,%4};" \
    :: "r"(a), "r"((v).x), "r"((v).y), "r"((v).z), "r"((v).w) : "memory")

#define LDSM4(r, a) asm volatile( \
    "ldmatrix.sync.aligned.m8n8.x4.shared.b16 {%0,%1,%2,%3}, [%4];" \
    : "=r"((r)[0]), "=r"((r)[1]), "=r"((r)[2]), "=r"((r)[3]) : "r"(a))

#define MMA(cc, a, b0_, b1_) asm volatile( \
    "mma.sync.aligned.m16n8k16.row.col.f32.bf16.bf16.f32 " \
    "{%0,%1,%2,%3},{%4,%5,%6,%7},{%8,%9},{%0,%1,%2,%3};" \
    : "+f"((cc)[0]), "+f"((cc)[1]), "+f"((cc)[2]), "+f"((cc)[3]) \
    : "r"((a)[0]), "r"((a)[1]), "r"((a)[2]), "r"((a)[3]), "r"(b0_), "r"(b1_))

// one split-term over all 8 independent accumulator chains (RAW spacing = 8 MMAs)
#define TERM(A_, B_) do { \
    _Pragma("unroll") \
    for (int mf_ = 0; mf_ < 2; mf_++) { \
        _Pragma("unroll") \
        for (int g_ = 0; g_ < 2; g_++) { \
            MMA(tmp[mf_][g_ * 2 + 0], A_[mf_], B_[g_][0], B_[g_][1]); \
            MMA(tmp[mf_][g_ * 2 + 1], A_[mf_], B_[g_][2], B_[g_][3]); \
        } \
    } } while (0)

// smem stage: 4 tiles (Ah Am Bh Bm), each [128 rows][64 bf16 = 128B] swizzled
#define TILE_B  16384
#define STAGE_B (4 * TILE_B)
#define SMEM_DYN (2 * STAGE_B)

__global__ __launch_bounds__(THREADS, 1)
void conv_mma_kernel(const float* __restrict__ x,
                     const float* __restrict__ Wg,
                     const float* __restrict__ bias,
                     float* __restrict__ out) {
    extern __shared__ char dsm[];
    __shared__ __align__(8) unsigned long long s_bar[4]; // full0 full1 empty0 empty1
    __shared__ int   s_tab[DD];
    __shared__ float s_ub[COUT];

    const uint32_t sbase = smem_u32(dsm);
    const uint32_t bar_full[2]  = { smem_u32(&s_bar[0]), smem_u32(&s_bar[1]) };
    const uint32_t bar_empty[2] = { smem_u32(&s_bar[2]), smem_u32(&s_bar[3]) };

    const int t   = threadIdx.x;
    const int wid = t >> 5;
    const int lid = t & 31;
    const int bm  = blockIdx.x * BM;

    // ---- init: offset table, bias fold, barriers ----
    for (int k = t; k < DD; k += THREADS) {
        int c = k / 9, r = k - 9 * c;
        int i = r / 3, j = r - 3 * i;
        s_tab[k] = ((c * LL + i * HWD + j) << 4) | r;
    }
    if (t < COUT) s_ub[t] = fmaf(__ldg(&bias[t]), INV_PI, -0.25f);
    if (t == 0) {
        MBAR_INIT(bar_full[0], 128); MBAR_INIT(bar_full[1], 128);
        MBAR_INIT(bar_empty[0], 256); MBAR_INIT(bar_empty[1], 256);
    }
    __syncthreads();

    // consumer accumulators (declared here so epilogue can see them)
    float acc[4][4][4];
    const int wm = wid & 1;       // 0-1 : m offset 64*wm
    const int wn = wid >> 1;      // 0-3 : n offset 32*wn

    if (wid >= 8) {
        // =============== producers (128 threads) ===============
        const int pt   = t - 256;          // 0..127 = row within tile
        const int gm   = bm + pt;
        const int img  = gm / LL;
        const int l    = gm - img * LL;
        const int y    = l / HWD;
        const int xx   = l - y * HWD;
        const float* xp = x + (long)img * (CIN * LL) + y * HWD + xx - (HWD + 1);

        uint32_t vmask = 0;
        #pragma unroll
        for (int i = 0; i < 3; i++)
            #pragma unroll
            for (int j = 0; j < 3; j++)
                if (((unsigned)(y + i - 1) < HWD) && ((unsigned)(xx + j - 1) < HWD))
                    vmask |= 1u << (i * 3 + j);

        const uint32_t swm   = (uint32_t)((pt & 7) << 4);
        const long     wrowB = (long)pt * DD;

        for (int c = 0; c < NCHUNK; c++) {
            const int s = c & 1;
            const int u = c >> 1;
            MBAR_WAIT(bar_empty[s], 1u ^ (u & 1));

            const uint32_t sb   = sbase + s * STAGE_B;
            const uint32_t arow = sb + pt * 128;
            const int kc = c * BK;

            // ---- A: im2col gather + 2-way bf16 split, row pt, 64 k ----
            #pragma unroll
            for (int g = 0; g < 8; g++) {
                uint32_t ph[4], pmv[4];
                #pragma unroll
                for (int p = 0; p < 4; p++) {
                    int k  = kc + g * 8 + p * 2;
                    int e0 = s_tab[k], e1 = s_tab[k + 1];
                    float v0 = ((vmask >> (e0 & 15)) & 1) ? __ldg(xp + (e0 >> 4)) : 0.f;
                    float v1 = ((vmask >> (e1 & 15)) & 1) ? __ldg(xp + (e1 >> 4)) : 0.f;
                    __nv_bfloat162 h2 = __floats2bfloat162_rn(v0, v1);
                    float r0 = v0 - __bfloat162float(h2.x);
                    float r1 = v1 - __bfloat162float(h2.y);
                    __nv_bfloat162 m2 = __floats2bfloat162_rn(r0, r1);
                    ph[p]  = *(uint32_t*)&h2;
                    pmv[p] = *(uint32_t*)&m2;
                }
                uint32_t off = ((uint32_t)(g * 16)) ^ swm;
                uint4 vh = make_uint4(ph[0], ph[1], ph[2], ph[3]);
                uint4 vm = make_uint4(pmv[0], pmv[1], pmv[2], pmv[3]);
                STS128(arow + 0 * TILE_B + off, vh);
                STS128(arow + 1 * TILE_B + off, vm);
            }

            // ---- B: copy pre-split weights, row pt, 64 k ----
            {
                const uint32_t brow = sb + 2 * TILE_B + pt * 128;
                const uint4* sH = (const uint4*)(g_Wh + wrowB + kc);
                const uint4* sM = (const uint4*)(g_Wm + wrowB + kc);
                #pragma unroll
                for (int q = 0; q < 8; q++) {
                    uint32_t off = ((uint32_t)(q * 16)) ^ swm;
                    uint4 vh = __ldg(&sH[q]);
                    uint4 vm = __ldg(&sM[q]);
                    STS128(brow + 0 * TILE_B + off, vh);
                    STS128(brow + 1 * TILE_B + off, vm);
                }
            }
            MBAR_ARRIVE(bar_full[s]);
        }
    } else {
        // =============== consumers (256 threads, 8 warps) ===============
        #pragma unroll
        for (int i = 0; i < 4; i++)
            #pragma unroll
            for (int j = 0; j < 4; j++)
                #pragma unroll
                for (int e = 0; e < 4; e++) acc[i][j][e] = 0.f;

        // ldmatrix lane-derived address components
        const int rA = lid & 15;
        const int kAl = (lid >> 4) * 16;
        const uint32_t swA = (uint32_t)((rA & 7) << 4);
        const uint32_t byA = (uint32_t)(rA * 128);
        const int rB = (lid & 7) + ((lid >> 4) << 3);
        const int kBl = ((lid >> 3) & 1) * 16;
        const uint32_t swB = (uint32_t)((lid & 7) << 4);
        const uint32_t byB = (uint32_t)(rB * 128);

        const uint32_t mbase = (uint32_t)(wm * 64 * 128);   // byte offset of warp m-rows
        const uint32_t nbase = (uint32_t)(wn * 32 * 128);   // byte offset of warp n-rows

        for (int c = 0; c < NCHUNK; c++) {
            const int s = c & 1;
            const int u = c >> 1;
            MBAR_WAIT(bar_full[s], (u & 1));

            const uint32_t sb  = sbase + s * STAGE_B;
            const uint32_t pAh = sb + 0 * TILE_B + mbase + byA;
            const uint32_t pAm = sb + 1 * TILE_B + mbase + byA;
            const uint32_t pBh = sb + 2 * TILE_B + nbase + byB;
            const uint32_t pBm = sb + 3 * TILE_B + nbase + byB;

            #pragma unroll
            for (int ks = 0; ks < 4; ks++) {
                const uint32_t aoff = (uint32_t)((ks * 32 + kAl)) ^ swA;
                const uint32_t boff = (uint32_t)((ks * 32 + kBl)) ^ swB;

                // B frags loaded ONCE per ks (shared by both m-halves)
                uint32_t Bh[2][4], Bm[2][4];
                #pragma unroll
                for (int g = 0; g < 2; g++) {
                    const uint32_t go = (uint32_t)(g * (16 * 128));
                    LDSM4(Bh[g], pBh + go + boff);
                    LDSM4(Bm[g], pBm + go + boff);
                }

                #pragma unroll
                for (int mh = 0; mh < 2; mh++) {
                    uint32_t Ah[2][4], Am[2][4];
                    #pragma unroll
                    for (int mf = 0; mf < 2; mf++) {
                        const uint32_t ro = (uint32_t)((mh * 2 + mf) * (16 * 128));
                        LDSM4(Ah[mf], pAh + ro + aoff);
                        LDSM4(Am[mf], pAm + ro + aoff);
                    }

                    // zeroed K=16 window accumulator (8 independent chains)
                    float tmp[2][4][4];
                    #pragma unroll
                    for (int i = 0; i < 2; i++)
                        #pragma unroll
                        for (int j = 0; j < 4; j++)
                            #pragma unroll
                            for (int e = 0; e < 4; e++) tmp[i][j][e] = 0.f;

                    // 3 terms only: mh, hm, hh (boundary rescue covers the rest)
                    TERM(Am, Bh);   // mh
                    TERM(Ah, Bm);   // hm
                    TERM(Ah, Bh);   // hh
                    // fold window into main acc with RN adds
                    #pragma unroll
                    for (int mf = 0; mf < 2; mf++)
                        #pragma unroll
                        for (int nf = 0; nf < 4; nf++)
                            #pragma unroll
                            for (int e = 0; e < 4; e++)
                                acc[mh * 2 + mf][nf][e] += tmp[mf][nf][e];
                }
            }
            MBAR_ARRIVE(bar_empty[s]);
        }
    }

    __syncthreads();

    // =============== epilogue: smem transpose + binarize + boundary rescue ===============
    float* scratch = (float*)dsm;          // [128 n][132 m] fp32 (reuses stage mem)
    if (wid < 8) {
        #pragma unroll
        for (int mf = 0; mf < 4; mf++) {
            const int m = wm * 64 + mf * 16 + (lid >> 2);
            #pragma unroll
            for (int nf = 0; nf < 4; nf++) {
                const int n = wn * 32 + nf * 8 + 2 * (lid & 3);
                scratch[n * 132 + m]           = acc[mf][nf][0];
                scratch[(n + 1) * 132 + m]     = acc[mf][nf][1];
                scratch[n * 132 + m + 8]       = acc[mf][nf][2];
                scratch[(n + 1) * 132 + m + 8] = acc[mf][nf][3];
            }
        }
    }
    __syncthreads();

    for (int i = t; i < COUT * 32; i += THREADS) {
        const int n  = i >> 5;
        const int mq = i & 31;
        float4 v = *(const float4*)&scratch[n * 132 + mq * 4];
        const int gm  = bm + mq * 4;
        const int img = gm / LL;        // LL % 4 == 0 -> same img for all 4 lanes
        const int l0  = gm - img * LL;
        const float ub = s_ub[n];
        float zs[4] = {v.x, v.y, v.z, v.w};
        float f[4];
        #pragma unroll
        for (int e = 0; e < 4; e++) {
            float u = fmaf(zs[e], INV_PI, ub);
            f[e] = u - floorf(u);
        }
        // boundary rescue: recompute near-threshold elements exactly in fp32.
        // BOTH boundary families: f ~ 0.5 AND f ~ 0 (== 1, frac wrap).
        #pragma unroll
        for (int e = 0; e < 4; e++) {
            float dist = fminf(fabsf(f[e] - 0.5f), fminf(f[e], 1.0f - f[e]));
            if (dist < EPS_F) {
                const int l  = l0 + e;
                const int y  = l / HWD;
                const int xq = l - y * HWD;
                const float* xb = x + (size_t)img * (CIN * LL) + y * HWD + xq - (HWD + 1);
                const float* wr = Wg + (size_t)n * DD;
                float zacc = 0.f;
                for (int cc = 0; cc < CIN; cc++) {
                    #pragma unroll
                    for (int ii = 0; ii < 3; ii++)
                        #pragma unroll
                        for (int jj = 0; jj < 3; jj++) {
                            bool ok = ((unsigned)(y + ii - 1) < HWD) &&
                                      ((unsigned)(xq + jj - 1) < HWD);
                            float xv = ok ? __ldg(xb + cc * LL + ii * HWD + jj) : 0.f;
                            zacc = fmaf(xv, __ldg(wr + cc * 9 + ii * 3 + jj), zacc);
                        }
                }
                float u = fmaf(zacc, INV_PI, ub);
                f[e] = u - floorf(u);
            }
        }
        float4 o;
        o.x = (f[0] < 0.5f) ? 1.f : 0.f;
        o.y = (f[1] < 0.5f) ? 1.f : 0.f;
        o.z = (f[2] < 0.5f) ? 1.f : 0.f;
        o.w = (f[3] < 0.5f) ? 1.f : 0.f;
        *(float4*)&out[((size_t)img * COUT + n) * LL + l0] = o;
    }
}

extern "C" void kernel_launch(void* const* d_in, const int* in_sizes, int n_in,
                              void* d_out, int out_size) {
    const float* x = (const float*)d_in[0];   // (32, 64, 56, 56)
    const float* W = (const float*)d_in[1];   // (128, 576)
    const float* b = (const float*)d_in[2];   // (128,)
    float* out = (float*)d_out;               // (32, 128, 56, 56)

    cudaFuncSetAttribute(conv_mma_kernel,
                         cudaFuncAttributeMaxDynamicSharedMemorySize, SMEM_DYN);

    split_w_kernel<<<(COUT * DD + 255) / 256, 256>>>(W);
    conv_mma_kernel<<<MM / BM, THREADS, SMEM_DYN>>>(x, W, b, out);
}

// round 12
// speedup vs baseline: 1.7234x; 1.7234x over previous
#include <cuda_runtime.h>
#include <cuda_bf16.h>
#include <stdint.h>
#include <math.h>

// Problem constants
#define CIN    64
#define HWD    56
#define LL     3136
#define COUT   128
#define MM     100352
#define DD     576
#define BM     128
#define BK     64
#define NCHUNK 9
#define THREADS 384          // warps 0-7 consumers, 8-11 producers
#define INV_PI 0.3183098861837907f
#define EPS_F  4e-4f         // boundary band (>> bound on |f err| of 3-term GEMM)
#define QCAP   1024          // rescue queue capacity (expected ~26/CTA)

// 2-way bf16 split of W, [COUT][DD] (k-contiguous = exactly what ldmatrix B wants)
__device__ __nv_bfloat16 g_Wh[COUT*DD];
__device__ __nv_bfloat16 g_Wm[COUT*DD];

__global__ void split_w_kernel(const float* __restrict__ W) {
    int i = blockIdx.x * 256 + threadIdx.x;
    if (i < COUT * DD) {
        float v = W[i];
        __nv_bfloat16 h = __float2bfloat16(v);
        float r1 = v - __bfloat162float(h);
        g_Wh[i] = h;
        g_Wm[i] = __float2bfloat16(r1);
    }
}

// ---------------- PTX helpers ----------------
__device__ __forceinline__ uint32_t smem_u32(const void* p) {
    uint32_t a;
    asm("{ .reg .u64 t; cvta.to.shared.u64 t, %1; cvt.u32.u64 %0, t; }" : "=r"(a) : "l"(p));
    return a;
}
#define MBAR_INIT(a, n) asm volatile("mbarrier.init.shared.b64 [%0], %1;" :: "r"(a), "r"(n) : "memory")
#define MBAR_ARRIVE(a)  asm volatile("mbarrier.arrive.shared.b64 _, [%0];" :: "r"(a) : "memory")
#define MBAR_WAIT(a, ph) do { \
    uint32_t _m = (a); uint32_t _p = (ph); uint32_t _d; \
    asm volatile("{\n\t.reg .pred p;\n\t" \
        "mbarrier.try_wait.parity.acquire.cta.shared::cta.b64 p, [%1], %2;\n\t" \
        "selp.b32 %0, 1, 0, p;\n\t}" : "=r"(_d) : "r"(_m), "r"(_p) : "memory"); \
    if (!_d) { \
        asm volatile("{\n\t.reg .pred P1;\n\t" \
            "WL_%=:\n\t" \
            "mbarrier.try_wait.parity.acquire.cta.shared::cta.b64 P1, [%0], %1, 0x989680;\n\t" \
            "@P1 bra.uni WD_%=;\n\t" \
            "bra.uni WL_%=;\n\t" \
            "WD_%=:\n\t}" :: "r"(_m), "r"(_p) : "memory"); \
    } } while (0)

#define STS128(a, v) asm volatile("st.shared.v4.b32 [%0], {%1,%2,%3,%4};" \
    :: "r"(a), "r"((v).x), "r"((v).y), "r"((v).z), "r"((v).w) : "memory")

#define LDSM4(r, a) asm volatile( \
    "ldmatrix.sync.aligned.m8n8.x4.shared.b16 {%0,%1,%2,%3}, [%4];" \
    : "=r"((r)[0]), "=r"((r)[1]), "=r"((r)[2]), "=r"((r)[3]) : "r"(a))

#define MMA(cc, a, b0_, b1_) asm volatile( \
    "mma.sync.aligned.m16n8k16.row.col.f32.bf16.bf16.f32 " \
    "{%0,%1,%2,%3},{%4,%5,%6,%7},{%8,%9},{%0,%1,%2,%3};" \
    : "+f"((cc)[0]), "+f"((cc)[1]), "+f"((cc)[2]), "+f"((cc)[3]) \
    : "r"((a)[0]), "r"((a)[1]), "r"((a)[2]), "r"((a)[3]), "r"(b0_), "r"(b1_))

// one split-term over all 8 independent accumulator chains (RAW spacing = 8 MMAs)
#define TERM(A_, B_) do { \
    _Pragma("unroll") \
    for (int mf_ = 0; mf_ < 2; mf_++) { \
        _Pragma("unroll") \
        for (int g_ = 0; g_ < 2; g_++) { \
            MMA(tmp[mf_][g_ * 2 + 0], A_[mf_], B_[g_][0], B_[g_][1]); \
            MMA(tmp[mf_][g_ * 2 + 1], A_[mf_], B_[g_][2], B_[g_][3]); \
        } \
    } } while (0)

// smem stage: 4 tiles (Ah Am Bh Bm), each [128 rows][64 bf16 = 128B] swizzled
#define TILE_B  16384
#define STAGE_B (4 * TILE_B)
#define SMEM_DYN (2 * STAGE_B)

__global__ __launch_bounds__(THREADS, 1)
void conv_mma_kernel(const float* __restrict__ x,
                     const float* __restrict__ Wg,
                     const float* __restrict__ bias,
                     float* __restrict__ out) {
    extern __shared__ char dsm[];
    __shared__ __align__(8) unsigned long long s_bar[4]; // full0 full1 empty0 empty1
    __shared__ int   s_tab[DD];
    __shared__ float s_ub[COUT];
    __shared__ int   s_qcnt;
    __shared__ int   s_queue[QCAP];

    const uint32_t sbase = smem_u32(dsm);
    const uint32_t bar_full[2]  = { smem_u32(&s_bar[0]), smem_u32(&s_bar[1]) };
    const uint32_t bar_empty[2] = { smem_u32(&s_bar[2]), smem_u32(&s_bar[3]) };

    const int t   = threadIdx.x;
    const int wid = t >> 5;
    const int lid = t & 31;
    const int bm  = blockIdx.x * BM;

    // ---- init: offset table, bias fold, barriers ----
    for (int k = t; k < DD; k += THREADS) {
        int c = k / 9, r = k - 9 * c;
        int i = r / 3, j = r - 3 * i;
        s_tab[k] = ((c * LL + i * HWD + j) << 4) | r;
    }
    if (t < COUT) s_ub[t] = fmaf(__ldg(&bias[t]), INV_PI, -0.25f);
    if (t == 0) {
        MBAR_INIT(bar_full[0], 128); MBAR_INIT(bar_full[1], 128);
        MBAR_INIT(bar_empty[0], 256); MBAR_INIT(bar_empty[1], 256);
        s_qcnt = 0;
    }
    __syncthreads();

    // consumer accumulators (declared here so epilogue can see them)
    float acc[4][4][4];
    const int wm = wid & 1;       // 0-1 : m offset 64*wm
    const int wn = wid >> 1;      // 0-3 : n offset 32*wn

    if (wid >= 8) {
        // =============== producers (128 threads) ===============
        const int pt   = t - 256;          // 0..127 = row within tile
        const int gm   = bm + pt;
        const int img  = gm / LL;
        const int l    = gm - img * LL;
        const int y    = l / HWD;
        const int xx   = l - y * HWD;
        const float* xp = x + (long)img * (CIN * LL) + y * HWD + xx - (HWD + 1);

        uint32_t vmask = 0;
        #pragma unroll
        for (int i = 0; i < 3; i++)
            #pragma unroll
            for (int j = 0; j < 3; j++)
                if (((unsigned)(y + i - 1) < HWD) && ((unsigned)(xx + j - 1) < HWD))
                    vmask |= 1u << (i * 3 + j);

        const uint32_t swm   = (uint32_t)((pt & 7) << 4);
        const long     wrowB = (long)pt * DD;

        for (int c = 0; c < NCHUNK; c++) {
            const int s = c & 1;
            const int u = c >> 1;
            MBAR_WAIT(bar_empty[s], 1u ^ (u & 1));

            const uint32_t sb   = sbase + s * STAGE_B;
            const uint32_t arow = sb + pt * 128;
            const int kc = c * BK;

            // ---- A: im2col gather + 2-way bf16 split, row pt, 64 k ----
            #pragma unroll
            for (int g = 0; g < 8; g++) {
                uint32_t ph[4], pmv[4];
                #pragma unroll
                for (int p = 0; p < 4; p++) {
                    int k  = kc + g * 8 + p * 2;
                    int e0 = s_tab[k], e1 = s_tab[k + 1];
                    float v0 = ((vmask >> (e0 & 15)) & 1) ? __ldg(xp + (e0 >> 4)) : 0.f;
                    float v1 = ((vmask >> (e1 & 15)) & 1) ? __ldg(xp + (e1 >> 4)) : 0.f;
                    __nv_bfloat162 h2 = __floats2bfloat162_rn(v0, v1);
                    float r0 = v0 - __bfloat162float(h2.x);
                    float r1 = v1 - __bfloat162float(h2.y);
                    __nv_bfloat162 m2 = __floats2bfloat162_rn(r0, r1);
                    ph[p]  = *(uint32_t*)&h2;
                    pmv[p] = *(uint32_t*)&m2;
                }
                uint32_t off = ((uint32_t)(g * 16)) ^ swm;
                uint4 vh = make_uint4(ph[0], ph[1], ph[2], ph[3]);
                uint4 vm = make_uint4(pmv[0], pmv[1], pmv[2], pmv[3]);
                STS128(arow + 0 * TILE_B + off, vh);
                STS128(arow + 1 * TILE_B + off, vm);
            }

            // ---- B: copy pre-split weights, row pt, 64 k ----
            {
                const uint32_t brow = sb + 2 * TILE_B + pt * 128;
                const uint4* sH = (const uint4*)(g_Wh + wrowB + kc);
                const uint4* sM = (const uint4*)(g_Wm + wrowB + kc);
                #pragma unroll
                for (int q = 0; q < 8; q++) {
                    uint32_t off = ((uint32_t)(q * 16)) ^ swm;
                    uint4 vh = __ldg(&sH[q]);
                    uint4 vm = __ldg(&sM[q]);
                    STS128(brow + 0 * TILE_B + off, vh);
                    STS128(brow + 1 * TILE_B + off, vm);
                }
            }
            MBAR_ARRIVE(bar_full[s]);
        }
    } else {
        // =============== consumers (256 threads, 8 warps) ===============
        #pragma unroll
        for (int i = 0; i < 4; i++)
            #pragma unroll
            for (int j = 0; j < 4; j++)
                #pragma unroll
                for (int e = 0; e < 4; e++) acc[i][j][e] = 0.f;

        // ldmatrix lane-derived address components
        const int rA = lid & 15;
        const int kAl = (lid >> 4) * 16;
        const uint32_t swA = (uint32_t)((rA & 7) << 4);
        const uint32_t byA = (uint32_t)(rA * 128);
        const int rB = (lid & 7) + ((lid >> 4) << 3);
        const int kBl = ((lid >> 3) & 1) * 16;
        const uint32_t swB = (uint32_t)((lid & 7) << 4);
        const uint32_t byB = (uint32_t)(rB * 128);

        const uint32_t mbase = (uint32_t)(wm * 64 * 128);   // byte offset of warp m-rows
        const uint32_t nbase = (uint32_t)(wn * 32 * 128);   // byte offset of warp n-rows

        for (int c = 0; c < NCHUNK; c++) {
            const int s = c & 1;
            const int u = c >> 1;
            MBAR_WAIT(bar_full[s], (u & 1));

            const uint32_t sb  = sbase + s * STAGE_B;
            const uint32_t pAh = sb + 0 * TILE_B + mbase + byA;
            const uint32_t pAm = sb + 1 * TILE_B + mbase + byA;
            const uint32_t pBh = sb + 2 * TILE_B + nbase + byB;
            const uint32_t pBm = sb + 3 * TILE_B + nbase + byB;

            #pragma unroll
            for (int ks = 0; ks < 4; ks++) {
                const uint32_t aoff = (uint32_t)((ks * 32 + kAl)) ^ swA;
                const uint32_t boff = (uint32_t)((ks * 32 + kBl)) ^ swB;

                // B frags loaded ONCE per ks (shared by both m-halves)
                uint32_t Bh[2][4], Bm[2][4];
                #pragma unroll
                for (int g = 0; g < 2; g++) {
                    const uint32_t go = (uint32_t)(g * (16 * 128));
                    LDSM4(Bh[g], pBh + go + boff);
                    LDSM4(Bm[g], pBm + go + boff);
                }

                #pragma unroll
                for (int mh = 0; mh < 2; mh++) {
                    uint32_t Ah[2][4], Am[2][4];
                    #pragma unroll
                    for (int mf = 0; mf < 2; mf++) {
                        const uint32_t ro = (uint32_t)((mh * 2 + mf) * (16 * 128));
                        LDSM4(Ah[mf], pAh + ro + aoff);
                        LDSM4(Am[mf], pAm + ro + aoff);
                    }

                    // zeroed K=16 window accumulator (8 independent chains)
                    float tmp[2][4][4];
                    #pragma unroll
                    for (int i = 0; i < 2; i++)
                        #pragma unroll
                        for (int j = 0; j < 4; j++)
                            #pragma unroll
                            for (int e = 0; e < 4; e++) tmp[i][j][e] = 0.f;

                    // 3 terms only: mh, hm, hh (boundary rescue covers the rest)
                    TERM(Am, Bh);   // mh
                    TERM(Ah, Bm);   // hm
                    TERM(Ah, Bh);   // hh
                    // fold window into main acc with RN adds
                    #pragma unroll
                    for (int mf = 0; mf < 2; mf++)
                        #pragma unroll
                        for (int nf = 0; nf < 4; nf++)
                            #pragma unroll
                            for (int e = 0; e < 4; e++)
                                acc[mh * 2 + mf][nf][e] += tmp[mf][nf][e];
                }
            }
            MBAR_ARRIVE(bar_empty[s]);
        }
    }

    __syncthreads();

    // =============== epilogue pass 1: transpose + binarize + queue boundary elems ===============
    float* scratch = (float*)dsm;          // [128 n][132 m] fp32 (reuses stage mem)
    if (wid < 8) {
        #pragma unroll
        for (int mf = 0; mf < 4; mf++) {
            const int m = wm * 64 + mf * 16 + (lid >> 2);
            #pragma unroll
            for (int nf = 0; nf < 4; nf++) {
                const int n = wn * 32 + nf * 8 + 2 * (lid & 3);
                scratch[n * 132 + m]           = acc[mf][nf][0];
                scratch[(n + 1) * 132 + m]     = acc[mf][nf][1];
                scratch[n * 132 + m + 8]       = acc[mf][nf][2];
                scratch[(n + 1) * 132 + m + 8] = acc[mf][nf][3];
            }
        }
    }
    __syncthreads();

    for (int i = t; i < COUT * 32; i += THREADS) {
        const int n  = i >> 5;
        const int mq = i & 31;
        float4 v = *(const float4*)&scratch[n * 132 + mq * 4];
        const int gm  = bm + mq * 4;
        const int img = gm / LL;        // LL % 4 == 0 -> same img for all 4 lanes
        const int l0  = gm - img * LL;
        const float ub = s_ub[n];
        float zs[4] = {v.x, v.y, v.z, v.w};
        float4 o;
        float* po = (float*)&o;
        #pragma unroll
        for (int e = 0; e < 4; e++) {
            float u = fmaf(zs[e], INV_PI, ub);
            float f = u - floorf(u);
            po[e] = (f < 0.5f) ? 1.f : 0.f;
            // queue near-boundary elements (both families: f~0.5 and f~0/1)
            float dist = fminf(fabsf(f - 0.5f), fminf(f, 1.0f - f));
            if (dist < EPS_F) {
                int pos = atomicAdd(&s_qcnt, 1);
                if (pos < QCAP) s_queue[pos] = (n << 8) | (mq * 4 + e);
            }
        }
        *(float4*)&out[((size_t)img * COUT + n) * LL + l0] = o;
    }
    __syncthreads();

    // =============== epilogue pass 2: thread-per-element exact fp32 rescue ===============
    // IMPORTANT: serial fp32 chain in ascending k order (cc -> ii -> jj), exactly
    // matching the R9 rescue whose rounding correlates with the reference.
    {
        const int nq = min(s_qcnt, QCAP);
        for (int q = t; q < nq; q += THREADS) {
            const int ent = s_queue[q];
            const int n   = ent >> 8;
            const int ml  = ent & 255;
            const int gm  = bm + ml;
            const int img = gm / LL;
            const int l   = gm - img * LL;
            const int y   = l / HWD;
            const int xq  = l - y * HWD;
            const float* xb = x + (size_t)img * (CIN * LL) + y * HWD + xq - (HWD + 1);
            const float* wr = Wg + (size_t)n * DD;

            float zacc = 0.f;
            for (int cc = 0; cc < CIN; cc++) {
                #pragma unroll
                for (int ii = 0; ii < 3; ii++)
                    #pragma unroll
                    for (int jj = 0; jj < 3; jj++) {
                        bool ok = ((unsigned)(y + ii - 1) < HWD) &&
                                  ((unsigned)(xq + jj - 1) < HWD);
                        float xv = ok ? __ldg(xb + cc * LL + ii * HWD + jj) : 0.f;
                        zacc = fmaf(xv, __ldg(wr + cc * 9 + ii * 3 + jj), zacc);
                    }
            }
            float u = fmaf(zacc, INV_PI, s_ub[n]);
            float f = u - floorf(u);
            out[((size_t)img * COUT + n) * LL + l] = (f < 0.5f) ? 1.f : 0.f;
        }
    }
}

extern "C" void kernel_launch(void* const* d_in, const int* in_sizes, int n_in,
                              void* d_out, int out_size) {
    const float* x = (const float*)d_in[0];   // (32, 64, 56, 56)
    const float* W = (const float*)d_in[1];   // (128, 576)
    const float* b = (const float*)d_in[2];   // (128,)
    float* out = (float*)d_out;               // (32, 128, 56, 56)

    cudaFuncSetAttribute(conv_mma_kernel,
                         cudaFuncAttributeMaxDynamicSharedMemorySize, SMEM_DYN);

    split_w_kernel<<<(COUT * DD + 255) / 256, 256>>>(W);
    conv_mma_kernel<<<MM / BM, THREADS, SMEM_DYN>>>(x, W, b, out);
}

// round 13
// speedup vs baseline: 1.7557x; 1.0187x over previous
#include <cuda_runtime.h>
#include <cuda_bf16.h>
#include <stdint.h>
#include <math.h>

// Problem constants
#define CIN    64
#define HWD    56
#define LL     3136
#define COUT   128
#define MM     100352
#define DD     576
#define BM     128
#define BK     64
#define NCHUNK 9
#define NSTAGE 3
#define THREADS 384          // warps 0-7 consumers, 8-11 producers
#define INV_PI 0.3183098861837907f
#define EPS_F  4e-4f         // boundary band (>> bound on |f err| of 3-term GEMM + RZ accum)
#define QCAP   1024          // rescue queue capacity (expected ~26/CTA)

// 2-way bf16 split of W, [COUT][DD] (k-contiguous = exactly what ldmatrix B wants)
__device__ __nv_bfloat16 g_Wh[COUT*DD];
__device__ __nv_bfloat16 g_Wm[COUT*DD];

__global__ void split_w_kernel(const float* __restrict__ W) {
    int i = blockIdx.x * 256 + threadIdx.x;
    if (i < COUT * DD) {
        float v = W[i];
        __nv_bfloat16 h = __float2bfloat16(v);
        float r1 = v - __bfloat162float(h);
        g_Wh[i] = h;
        g_Wm[i] = __float2bfloat16(r1);
    }
}

// ---------------- PTX helpers ----------------
__device__ __forceinline__ uint32_t smem_u32(const void* p) {
    uint32_t a;
    asm("{ .reg .u64 t; cvta.to.shared.u64 t, %1; cvt.u32.u64 %0, t; }" : "=r"(a) : "l"(p));
    return a;
}
#define MBAR_INIT(a, n) asm volatile("mbarrier.init.shared.b64 [%0], %1;" :: "r"(a), "r"(n) : "memory")
#define MBAR_ARRIVE(a)  asm volatile("mbarrier.arrive.shared.b64 _, [%0];" :: "r"(a) : "memory")
#define MBAR_WAIT(a, ph) do { \
    uint32_t _m = (a); uint32_t _p = (ph); uint32_t _d; \
    asm volatile("{\n\t.reg .pred p;\n\t" \
        "mbarrier.try_wait.parity.acquire.cta.shared::cta.b64 p, [%1], %2;\n\t" \
        "selp.b32 %0, 1, 0, p;\n\t}" : "=r"(_d) : "r"(_m), "r"(_p) : "memory"); \
    if (!_d) { \
        asm volatile("{\n\t.reg .pred P1;\n\t" \
            "WL_%=:\n\t" \
            "mbarrier.try_wait.parity.acquire.cta.shared::cta.b64 P1, [%0], %1, 0x989680;\n\t" \
            "@P1 bra.uni WD_%=;\n\t" \
            "bra.uni WL_%=;\n\t" \
            "WD_%=:\n\t}" :: "r"(_m), "r"(_p) : "memory"); \
    } } while (0)

#define STS128(a, v) asm volatile("st.shared.v4.b32 [%0], {%1,%2,%3,%4};" \
    :: "r"(a), "r"((v).x), "r"((v).y), "r"((v).z), "r"((v).w) : "memory")

#define LDSM4(r, a) asm volatile( \
    "ldmatrix.sync.aligned.m8n8.x4.shared.b16 {%0,%1,%2,%3}, [%4];" \
    : "=r"((r)[0]), "=r"((r)[1]), "=r"((r)[2]), "=r"((r)[3]) : "r"(a))

#define MMA(cc, a, b0_, b1_) asm volatile( \
    "mma.sync.aligned.m16n8k16.row.col.f32.bf16.bf16.f32 " \
    "{%0,%1,%2,%3},{%4,%5,%6,%7},{%8,%9},{%0,%1,%2,%3};" \
    : "+f"((cc)[0]), "+f"((cc)[1]), "+f"((cc)[2]), "+f"((cc)[3]) \
    : "r"((a)[0]), "r"((a)[1]), "r"((a)[2]), "r"((a)[3]), "r"(b0_), "r"(b1_))

// one split-term over all 8 independent accumulator chains of this m-half
#define TERM(A_, B_, MH_) do { \
    _Pragma("unroll") \
    for (int mf_ = 0; mf_ < 2; mf_++) { \
        _Pragma("unroll") \
        for (int g_ = 0; g_ < 2; g_++) { \
            MMA(acc[(MH_) * 2 + mf_][g_ * 2 + 0], A_[mf_], B_[g_][0], B_[g_][1]); \
            MMA(acc[(MH_) * 2 + mf_][g_ * 2 + 1], A_[mf_], B_[g_][2], B_[g_][3]); \
        } \
    } } while (0)

// smem stage: 4 tiles (Ah Am Bh Bm), each [128 rows][64 bf16 = 128B] swizzled
#define TILE_B  16384
#define STAGE_B (4 * TILE_B)
#define SMEM_DYN (NSTAGE * STAGE_B)

__global__ __launch_bounds__(THREADS, 1)
void conv_mma_kernel(const float* __restrict__ x,
                     const float* __restrict__ Wg,
                     const float* __restrict__ bias,
                     float* __restrict__ out) {
    extern __shared__ char dsm[];
    __shared__ __align__(8) unsigned long long s_bar[2 * NSTAGE]; // full[3], empty[3]
    __shared__ int   s_tab[DD];
    __shared__ float s_ub[COUT];
    __shared__ int   s_qcnt;
    __shared__ int   s_queue[QCAP];

    const uint32_t sbase = smem_u32(dsm);
    uint32_t bar_full[NSTAGE], bar_empty[NSTAGE];
    #pragma unroll
    for (int s = 0; s < NSTAGE; s++) {
        bar_full[s]  = smem_u32(&s_bar[s]);
        bar_empty[s] = smem_u32(&s_bar[NSTAGE + s]);
    }

    const int t   = threadIdx.x;
    const int wid = t >> 5;
    const int lid = t & 31;
    const int bm  = blockIdx.x * BM;

    // ---- init: offset table, bias fold, barriers ----
    for (int k = t; k < DD; k += THREADS) {
        int c = k / 9, r = k - 9 * c;
        int i = r / 3, j = r - 3 * i;
        s_tab[k] = ((c * LL + i * HWD + j) << 4) | r;
    }
    if (t < COUT) s_ub[t] = fmaf(__ldg(&bias[t]), INV_PI, -0.25f);
    if (t == 0) {
        #pragma unroll
        for (int s = 0; s < NSTAGE; s++) {
            MBAR_INIT(bar_full[s], 128);
            MBAR_INIT(bar_empty[s], 256);
        }
        s_qcnt = 0;
    }
    __syncthreads();

    // consumer accumulators (declared here so epilogue can see them)
    float acc[4][4][4];
    const int wm = wid & 1;       // 0-1 : m offset 64*wm
    const int wn = wid >> 1;      // 0-3 : n offset 32*wn

    if (wid >= 8) {
        // =============== producers (128 threads) ===============
        const int pt   = t - 256;          // 0..127 = row within tile
        const int gm   = bm + pt;
        const int img  = gm / LL;
        const int l    = gm - img * LL;
        const int y    = l / HWD;
        const int xx   = l - y * HWD;
        const float* xp = x + (long)img * (CIN * LL) + y * HWD + xx - (HWD + 1);

        uint32_t vmask = 0;
        #pragma unroll
        for (int i = 0; i < 3; i++)
            #pragma unroll
            for (int j = 0; j < 3; j++)
                if (((unsigned)(y + i - 1) < HWD) && ((unsigned)(xx + j - 1) < HWD))
                    vmask |= 1u << (i * 3 + j);

        const uint32_t swm   = (uint32_t)((pt & 7) << 4);
        const long     wrowB = (long)pt * DD;

        for (int c = 0; c < NCHUNK; c++) {
            const int s = c % NSTAGE;
            const int u = c / NSTAGE;
            MBAR_WAIT(bar_empty[s], 1u ^ (u & 1));

            const uint32_t sb   = sbase + s * STAGE_B;
            const uint32_t arow = sb + pt * 128;
            const int kc = c * BK;

            // ---- A: im2col gather + 2-way bf16 split, row pt, 64 k ----
            #pragma unroll
            for (int g = 0; g < 8; g++) {
                uint32_t ph[4], pmv[4];
                #pragma unroll
                for (int p = 0; p < 4; p++) {
                    int k  = kc + g * 8 + p * 2;
                    int e0 = s_tab[k], e1 = s_tab[k + 1];
                    float v0 = ((vmask >> (e0 & 15)) & 1) ? __ldg(xp + (e0 >> 4)) : 0.f;
                    float v1 = ((vmask >> (e1 & 15)) & 1) ? __ldg(xp + (e1 >> 4)) : 0.f;
                    __nv_bfloat162 h2 = __floats2bfloat162_rn(v0, v1);
                    float r0 = v0 - __bfloat162float(h2.x);
                    float r1 = v1 - __bfloat162float(h2.y);
                    __nv_bfloat162 m2 = __floats2bfloat162_rn(r0, r1);
                    ph[p]  = *(uint32_t*)&h2;
                    pmv[p] = *(uint32_t*)&m2;
                }
                uint32_t off = ((uint32_t)(g * 16)) ^ swm;
                uint4 vh = make_uint4(ph[0], ph[1], ph[2], ph[3]);
                uint4 vm = make_uint4(pmv[0], pmv[1], pmv[2], pmv[3]);
                STS128(arow + 0 * TILE_B + off, vh);
                STS128(arow + 1 * TILE_B + off, vm);
            }

            // ---- B: copy pre-split weights, row pt, 64 k ----
            {
                const uint32_t brow = sb + 2 * TILE_B + pt * 128;
                const uint4* sH = (const uint4*)(g_Wh + wrowB + kc);
                const uint4* sM = (const uint4*)(g_Wm + wrowB + kc);
                #pragma unroll
                for (int q = 0; q < 8; q++) {
                    uint32_t off = ((uint32_t)(q * 16)) ^ swm;
                    uint4 vh = __ldg(&sH[q]);
                    uint4 vm = __ldg(&sM[q]);
                    STS128(brow + 0 * TILE_B + off, vh);
                    STS128(brow + 1 * TILE_B + off, vm);
                }
            }
            MBAR_ARRIVE(bar_full[s]);
        }
    } else {
        // =============== consumers (256 threads, 8 warps) ===============
        #pragma unroll
        for (int i = 0; i < 4; i++)
            #pragma unroll
            for (int j = 0; j < 4; j++)
                #pragma unroll
                for (int e = 0; e < 4; e++) acc[i][j][e] = 0.f;

        // ldmatrix lane-derived address components
        const int rA = lid & 15;
        const int kAl = (lid >> 4) * 16;
        const uint32_t swA = (uint32_t)((rA & 7) << 4);
        const uint32_t byA = (uint32_t)(rA * 128);
        const int rB = (lid & 7) + ((lid >> 4) << 3);
        const int kBl = ((lid >> 3) & 1) * 16;
        const uint32_t swB = (uint32_t)((lid & 7) << 4);
        const uint32_t byB = (uint32_t)(rB * 128);

        const uint32_t mbase = (uint32_t)(wm * 64 * 128);   // byte offset of warp m-rows
        const uint32_t nbase = (uint32_t)(wn * 32 * 128);   // byte offset of warp n-rows

        for (int c = 0; c < NCHUNK; c++) {
            const int s = c % NSTAGE;
            const int u = c / NSTAGE;
            MBAR_WAIT(bar_full[s], (u & 1));

            const uint32_t sb  = sbase + s * STAGE_B;
            const uint32_t pAh = sb + 0 * TILE_B + mbase + byA;
            const uint32_t pAm = sb + 1 * TILE_B + mbase + byA;
            const uint32_t pBh = sb + 2 * TILE_B + nbase + byB;
            const uint32_t pBm = sb + 3 * TILE_B + nbase + byB;

            #pragma unroll
            for (int ks = 0; ks < 4; ks++) {
                const uint32_t aoff = (uint32_t)((ks * 32 + kAl)) ^ swA;
                const uint32_t boff = (uint32_t)((ks * 32 + kBl)) ^ swB;

                // B frags loaded ONCE per ks (shared by both m-halves)
                uint32_t Bh[2][4], Bm[2][4];
                #pragma unroll
                for (int g = 0; g < 2; g++) {
                    const uint32_t go = (uint32_t)(g * (16 * 128));
                    LDSM4(Bh[g], pBh + go + boff);
                    LDSM4(Bm[g], pBm + go + boff);
                }

                #pragma unroll
                for (int mh = 0; mh < 2; mh++) {
                    uint32_t Ah[2][4], Am[2][4];
                    #pragma unroll
                    for (int mf = 0; mf < 2; mf++) {
                        const uint32_t ro = (uint32_t)((mh * 2 + mf) * (16 * 128));
                        LDSM4(Ah[mf], pAh + ro + aoff);
                        LDSM4(Am[mf], pAm + ro + aoff);
                    }

                    // 3 terms, direct accumulation into acc (rescue covers the
                    // dropped mm term AND the RZ accumulation error)
                    TERM(Am, Bh, mh);   // mh
                    TERM(Ah, Bm, mh);   // hm
                    TERM(Ah, Bh, mh);   // hh
                }
            }
            MBAR_ARRIVE(bar_empty[s]);
        }
    }

    __syncthreads();

    // =============== epilogue pass 1: transpose + binarize + queue boundary elems ===============
    float* scratch = (float*)dsm;          // [128 n][132 m] fp32 (reuses stage mem)
    if (wid < 8) {
        #pragma unroll
        for (int mf = 0; mf < 4; mf++) {
            const int m = wm * 64 + mf * 16 + (lid >> 2);
            #pragma unroll
            for (int nf = 0; nf < 4; nf++) {
                const int n = wn * 32 + nf * 8 + 2 * (lid & 3);
                scratch[n * 132 + m]           = acc[mf][nf][0];
                scratch[(n + 1) * 132 + m]     = acc[mf][nf][1];
                scratch[n * 132 + m + 8]       = acc[mf][nf][2];
                scratch[(n + 1) * 132 + m + 8] = acc[mf][nf][3];
            }
        }
    }
    __syncthreads();

    for (int i = t; i < COUT * 32; i += THREADS) {
        const int n  = i >> 5;
        const int mq = i & 31;
        float4 v = *(const float4*)&scratch[n * 132 + mq * 4];
        const int gm  = bm + mq * 4;
        const int img = gm / LL;        // LL % 4 == 0 -> same img for all 4 lanes
        const int l0  = gm - img * LL;
        const float ub = s_ub[n];
        float zs[4] = {v.x, v.y, v.z, v.w};
        float4 o;
        float* po = (float*)&o;
        #pragma unroll
        for (int e = 0; e < 4; e++) {
            float u = fmaf(zs[e], INV_PI, ub);
            float f = u - floorf(u);
            po[e] = (f < 0.5f) ? 1.f : 0.f;
            // queue near-boundary elements (both families: f~0.5 and f~0/1)
            float dist = fminf(fabsf(f - 0.5f), fminf(f, 1.0f - f));
            if (dist < EPS_F) {
                int pos = atomicAdd(&s_qcnt, 1);
                if (pos < QCAP) s_queue[pos] = (n << 8) | (mq * 4 + e);
            }
        }
        *(float4*)&out[((size_t)img * COUT + n) * LL + l0] = o;
    }
    __syncthreads();

    // =============== epilogue pass 2: thread-per-element exact fp32 rescue ===============
    // serial fp32 chain in ascending k order (cc -> ii -> jj): rounding correlates
    // with the reference accumulation (empirically fewest flips; R9/R11-proven)
    {
        const int nq = min(s_qcnt, QCAP);
        for (int q = t; q < nq; q += THREADS) {
            const int ent = s_queue[q];
            const int n   = ent >> 8;
            const int ml  = ent & 255;
            const int gm  = bm + ml;
            const int img = gm / LL;
            const int l   = gm - img * LL;
            const int y   = l / HWD;
            const int xq  = l - y * HWD;
            const float* xb = x + (size_t)img * (CIN * LL) + y * HWD + xq - (HWD + 1);
            const float* wr = Wg + (size_t)n * DD;

            float zacc = 0.f;
            for (int cc = 0; cc < CIN; cc++) {
                #pragma unroll
                for (int ii = 0; ii < 3; ii++)
                    #pragma unroll
                    for (int jj = 0; jj < 3; jj++) {
                        bool ok = ((unsigned)(y + ii - 1) < HWD) &&
                                  ((unsigned)(xq + jj - 1) < HWD);
                        float xv = ok ? __ldg(xb + cc * LL + ii * HWD + jj) : 0.f;
                        zacc = fmaf(xv, __ldg(wr + cc * 9 + ii * 3 + jj), zacc);
                    }
            }
            float u = fmaf(zacc, INV_PI, s_ub[n]);
            float f = u - floorf(u);
            out[((size_t)img * COUT + n) * LL + l] = (f < 0.5f) ? 1.f : 0.f;
        }
    }
}

extern "C" void kernel_launch(void* const* d_in, const int* in_sizes, int n_in,
                              void* d_out, int out_size) {
    const float* x = (const float*)d_in[0];   // (32, 64, 56, 56)
    const float* W = (const float*)d_in[1];   // (128, 576)
    const float* b = (const float*)d_in[2];   // (128,)
    float* out = (float*)d_out;               // (32, 128, 56, 56)

    cudaFuncSetAttribute(conv_mma_kernel,
                         cudaFuncAttributeMaxDynamicSharedMemorySize, SMEM_DYN);

    split_w_kernel<<<(COUT * DD + 255) / 256, 256>>>(W);
    conv_mma_kernel<<<MM / BM, THREADS, SMEM_DYN>>>(x, W, b, out);
}

// round 14
// speedup vs baseline: 1.9869x; 1.1317x over previous
#include <cuda_runtime.h>
#include <cuda_bf16.h>
#include <stdint.h>
#include <math.h>

// Problem constants
#define CIN    64
#define HWD    56
#define LL     3136
#define COUT   128
#define MM     100352
#define DD     576
#define BM     128
#define BK     64
#define NCHUNK 9
#define NSTAGE 3
#define THREADS 512          // warps 0-7 consumers, 8-15 producers
#define INV_PI 0.3183098861837907f
#define EPS_F  4e-4f         // boundary band (>> bound on |f err| of 3-term GEMM + RZ accum)
#define QCAP   1024          // rescue queue capacity (expected ~26/CTA)

// 2-way bf16 split of W, [COUT][DD] (k-contiguous = exactly what ldmatrix B wants)
__device__ __nv_bfloat16 g_Wh[COUT*DD];
__device__ __nv_bfloat16 g_Wm[COUT*DD];

__global__ void split_w_kernel(const float* __restrict__ W) {
    int i = blockIdx.x * 256 + threadIdx.x;
    if (i < COUT * DD) {
        float v = W[i];
        __nv_bfloat16 h = __float2bfloat16(v);
        float r1 = v - __bfloat162float(h);
        g_Wh[i] = h;
        g_Wm[i] = __float2bfloat16(r1);
    }
}

// ---------------- PTX helpers ----------------
__device__ __forceinline__ uint32_t smem_u32(const void* p) {
    uint32_t a;
    asm("{ .reg .u64 t; cvta.to.shared.u64 t, %1; cvt.u32.u64 %0, t; }" : "=r"(a) : "l"(p));
    return a;
}
#define MBAR_INIT(a, n) asm volatile("mbarrier.init.shared.b64 [%0], %1;" :: "r"(a), "r"(n) : "memory")
#define MBAR_ARRIVE(a)  asm volatile("mbarrier.arrive.shared.b64 _, [%0];" :: "r"(a) : "memory")
#define MBAR_WAIT(a, ph) do { \
    uint32_t _m = (a); uint32_t _p = (ph); uint32_t _d; \
    asm volatile("{\n\t.reg .pred p;\n\t" \
        "mbarrier.try_wait.parity.acquire.cta.shared::cta.b64 p, [%1], %2;\n\t" \
        "selp.b32 %0, 1, 0, p;\n\t}" : "=r"(_d) : "r"(_m), "r"(_p) : "memory"); \
    if (!_d) { \
        asm volatile("{\n\t.reg .pred P1;\n\t" \
            "WL_%=:\n\t" \
            "mbarrier.try_wait.parity.acquire.cta.shared::cta.b64 P1, [%0], %1, 0x989680;\n\t" \
            "@P1 bra.uni WD_%=;\n\t" \
            "bra.uni WL_%=;\n\t" \
            "WD_%=:\n\t}" :: "r"(_m), "r"(_p) : "memory"); \
    } } while (0)

#define STS128(a, v) asm volatile("st.shared.v4.b32 [%0], {%1,%2,%3,%4};" \
    :: "r"(a), "r"((v).x), "r"((v).y), "r"((v).z), "r"((v).w) : "memory")

#define LDSM4(r, a) asm volatile( \
    "ldmatrix.sync.aligned.m8n8.x4.shared.b16 {%0,%1,%2,%3}, [%4];" \
    : "=r"((r)[0]), "=r"((r)[1]), "=r"((r)[2]), "=r"((r)[3]) : "r"(a))

#define MMA(cc, a, b0_, b1_) asm volatile( \
    "mma.sync.aligned.m16n8k16.row.col.f32.bf16.bf16.f32 " \
    "{%0,%1,%2,%3},{%4,%5,%6,%7},{%8,%9},{%0,%1,%2,%3};" \
    : "+f"((cc)[0]), "+f"((cc)[1]), "+f"((cc)[2]), "+f"((cc)[3]) \
    : "r"((a)[0]), "r"((a)[1]), "r"((a)[2]), "r"((a)[3]), "r"(b0_), "r"(b1_))

// one split-term over all 8 independent accumulator chains of this m-half
#define TERM(A_, B_, MH_) do { \
    _Pragma("unroll") \
    for (int mf_ = 0; mf_ < 2; mf_++) { \
        _Pragma("unroll") \
        for (int g_ = 0; g_ < 2; g_++) { \
            MMA(acc[(MH_) * 2 + mf_][g_ * 2 + 0], A_[mf_], B_[g_][0], B_[g_][1]); \
            MMA(acc[(MH_) * 2 + mf_][g_ * 2 + 1], A_[mf_], B_[g_][2], B_[g_][3]); \
        } \
    } } while (0)

// smem stage: 4 tiles (Ah Am Bh Bm), each [128 rows][64 bf16 = 128B] swizzled
#define TILE_B  16384
#define STAGE_B (4 * TILE_B)
#define SMEM_DYN (NSTAGE * STAGE_B)

__global__ __launch_bounds__(THREADS, 1)
void conv_mma_kernel(const float* __restrict__ x,
                     const float* __restrict__ Wg,
                     const float* __restrict__ bias,
                     float* __restrict__ out) {
    extern __shared__ char dsm[];
    __shared__ __align__(8) unsigned long long s_bar[2 * NSTAGE]; // full[3], empty[3]
    __shared__ int   s_tab[DD];
    __shared__ float s_ub[COUT];
    __shared__ int   s_qcnt;
    __shared__ int   s_queue[QCAP];

    const uint32_t sbase = smem_u32(dsm);
    uint32_t bar_full[NSTAGE], bar_empty[NSTAGE];
    #pragma unroll
    for (int s = 0; s < NSTAGE; s++) {
        bar_full[s]  = smem_u32(&s_bar[s]);
        bar_empty[s] = smem_u32(&s_bar[NSTAGE + s]);
    }

    const int t   = threadIdx.x;
    const int wid = t >> 5;
    const int lid = t & 31;
    const int bm  = blockIdx.x * BM;

    // ---- init: offset table, bias fold, barriers ----
    for (int k = t; k < DD; k += THREADS) {
        int c = k / 9, r = k - 9 * c;
        int i = r / 3, j = r - 3 * i;
        s_tab[k] = ((c * LL + i * HWD + j) << 4) | r;
    }
    if (t < COUT) s_ub[t] = fmaf(__ldg(&bias[t]), INV_PI, -0.25f);
    if (t == 0) {
        #pragma unroll
        for (int s = 0; s < NSTAGE; s++) {
            MBAR_INIT(bar_full[s], 256);    // 256 producer threads arrive
            MBAR_INIT(bar_empty[s], 256);   // 256 consumer threads arrive
        }
        s_qcnt = 0;
    }
    __syncthreads();

    // consumer accumulators (declared here so epilogue can see them)
    float acc[4][4][4];
    const int wm = wid & 1;       // 0-1 : m offset 64*wm
    const int wn = (wid >> 1) & 3; // 0-3 : n offset 32*wn (valid for wid<8)

    if (wid >= 8) {
        // =============== producers (256 threads, 8 warps) ===============
        const int ptt  = t - 256;          // 0..255
        const int pt   = ptt & 127;        // row within tile
        const int kh   = (ptt >> 7) * 32;  // k-half within chunk: 0 or 32
        const int gm   = bm + pt;
        const int img  = gm / LL;
        const int l    = gm - img * LL;
        const int y    = l / HWD;
        const int xx   = l - y * HWD;
        const float* xp = x + (long)img * (CIN * LL) + y * HWD + xx - (HWD + 1);

        uint32_t vmask = 0;
        #pragma unroll
        for (int i = 0; i < 3; i++)
            #pragma unroll
            for (int j = 0; j < 3; j++)
                if (((unsigned)(y + i - 1) < HWD) && ((unsigned)(xx + j - 1) < HWD))
                    vmask |= 1u << (i * 3 + j);

        const uint32_t swm   = (uint32_t)((pt & 7) << 4);
        const long     wrowB = (long)pt * DD;

        for (int c = 0; c < NCHUNK; c++) {
            const int s = c % NSTAGE;
            const int u = c / NSTAGE;
            MBAR_WAIT(bar_empty[s], 1u ^ (u & 1));

            const uint32_t sb   = sbase + s * STAGE_B;
            const uint32_t arow = sb + pt * 128;
            const int kc = c * BK;

            // ---- A: im2col gather + 2-way bf16 split, row pt, 32 k (this half) ----
            #pragma unroll
            for (int g = 0; g < 4; g++) {
                uint32_t ph[4], pmv[4];
                #pragma unroll
                for (int p = 0; p < 4; p++) {
                    int k  = kc + kh + g * 8 + p * 2;
                    int e0 = s_tab[k], e1 = s_tab[k + 1];
                    float v0 = ((vmask >> (e0 & 15)) & 1) ? __ldg(xp + (e0 >> 4)) : 0.f;
                    float v1 = ((vmask >> (e1 & 15)) & 1) ? __ldg(xp + (e1 >> 4)) : 0.f;
                    __nv_bfloat162 h2 = __floats2bfloat162_rn(v0, v1);
                    float r0 = v0 - __bfloat162float(h2.x);
                    float r1 = v1 - __bfloat162float(h2.y);
                    __nv_bfloat162 m2 = __floats2bfloat162_rn(r0, r1);
                    ph[p]  = *(uint32_t*)&h2;
                    pmv[p] = *(uint32_t*)&m2;
                }
                uint32_t off = ((uint32_t)(kh * 2 + g * 16)) ^ swm;
                uint4 vh = make_uint4(ph[0], ph[1], ph[2], ph[3]);
                uint4 vm = make_uint4(pmv[0], pmv[1], pmv[2], pmv[3]);
                STS128(arow + 0 * TILE_B + off, vh);
                STS128(arow + 1 * TILE_B + off, vm);
            }

            // ---- B: copy pre-split weights, row pt, 32 k (this half) ----
            {
                const uint32_t brow = sb + 2 * TILE_B + pt * 128;
                const uint4* sH = (const uint4*)(g_Wh + wrowB + kc + kh);
                const uint4* sM = (const uint4*)(g_Wm + wrowB + kc + kh);
                #pragma unroll
                for (int q = 0; q < 4; q++) {
                    uint32_t off = ((uint32_t)(kh * 2 + q * 16)) ^ swm;
                    uint4 vh = __ldg(&sH[q]);
                    uint4 vm = __ldg(&sM[q]);
                    STS128(brow + 0 * TILE_B + off, vh);
                    STS128(brow + 1 * TILE_B + off, vm);
                }
            }
            MBAR_ARRIVE(bar_full[s]);
        }
    } else {
        // =============== consumers (256 threads, 8 warps) ===============
        #pragma unroll
        for (int i = 0; i < 4; i++)
            #pragma unroll
            for (int j = 0; j < 4; j++)
                #pragma unroll
                for (int e = 0; e < 4; e++) acc[i][j][e] = 0.f;

        // ldmatrix lane-derived address components
        const int rA = lid & 15;
        const int kAl = (lid >> 4) * 16;
        const uint32_t swA = (uint32_t)((rA & 7) << 4);
        const uint32_t byA = (uint32_t)(rA * 128);
        const int rB = (lid & 7) + ((lid >> 4) << 3);
        const int kBl = ((lid >> 3) & 1) * 16;
        const uint32_t swB = (uint32_t)((lid & 7) << 4);
        const uint32_t byB = (uint32_t)(rB * 128);

        const uint32_t mbase = (uint32_t)(wm * 64 * 128);   // byte offset of warp m-rows
        const uint32_t nbase = (uint32_t)(wn * 32 * 128);   // byte offset of warp n-rows

        for (int c = 0; c < NCHUNK; c++) {
            const int s = c % NSTAGE;
            const int u = c / NSTAGE;
            MBAR_WAIT(bar_full[s], (u & 1));

            const uint32_t sb  = sbase + s * STAGE_B;
            const uint32_t pAh = sb + 0 * TILE_B + mbase + byA;
            const uint32_t pAm = sb + 1 * TILE_B + mbase + byA;
            const uint32_t pBh = sb + 2 * TILE_B + nbase + byB;
            const uint32_t pBm = sb + 3 * TILE_B + nbase + byB;

            #pragma unroll
            for (int ks = 0; ks < 4; ks++) {
                const uint32_t aoff = (uint32_t)((ks * 32 + kAl)) ^ swA;
                const uint32_t boff = (uint32_t)((ks * 32 + kBl)) ^ swB;

                // B frags loaded ONCE per ks (shared by both m-halves)
                uint32_t Bh[2][4], Bm[2][4];
                #pragma unroll
                for (int g = 0; g < 2; g++) {
                    const uint32_t go = (uint32_t)(g * (16 * 128));
                    LDSM4(Bh[g], pBh + go + boff);
                    LDSM4(Bm[g], pBm + go + boff);
                }

                #pragma unroll
                for (int mh = 0; mh < 2; mh++) {
                    uint32_t Ah[2][4], Am[2][4];
                    #pragma unroll
                    for (int mf = 0; mf < 2; mf++) {
                        const uint32_t ro = (uint32_t)((mh * 2 + mf) * (16 * 128));
                        LDSM4(Ah[mf], pAh + ro + aoff);
                        LDSM4(Am[mf], pAm + ro + aoff);
                    }

                    // 3 terms, direct accumulation into acc (rescue covers the
                    // dropped mm term AND the RZ accumulation error)
                    TERM(Am, Bh, mh);   // mh
                    TERM(Ah, Bm, mh);   // hm
                    TERM(Ah, Bh, mh);   // hh
                }
            }
            MBAR_ARRIVE(bar_empty[s]);
        }
    }

    __syncthreads();

    // =============== epilogue pass 1: transpose + binarize + queue boundary elems ===============
    float* scratch = (float*)dsm;          // [128 n][132 m] fp32 (reuses stage mem)
    if (wid < 8) {
        #pragma unroll
        for (int mf = 0; mf < 4; mf++) {
            const int m = wm * 64 + mf * 16 + (lid >> 2);
            #pragma unroll
            for (int nf = 0; nf < 4; nf++) {
                const int n = wn * 32 + nf * 8 + 2 * (lid & 3);
                scratch[n * 132 + m]           = acc[mf][nf][0];
                scratch[(n + 1) * 132 + m]     = acc[mf][nf][1];
                scratch[n * 132 + m + 8]       = acc[mf][nf][2];
                scratch[(n + 1) * 132 + m + 8] = acc[mf][nf][3];
            }
        }
    }
    __syncthreads();

    for (int i = t; i < COUT * 32; i += THREADS) {
        const int n  = i >> 5;
        const int mq = i & 31;
        float4 v = *(const float4*)&scratch[n * 132 + mq * 4];
        const int gm  = bm + mq * 4;
        const int img = gm / LL;        // LL % 4 == 0 -> same img for all 4 lanes
        const int l0  = gm - img * LL;
        const float ub = s_ub[n];
        float zs[4] = {v.x, v.y, v.z, v.w};
        float4 o;
        float* po = (float*)&o;
        #pragma unroll
        for (int e = 0; e < 4; e++) {
            float u = fmaf(zs[e], INV_PI, ub);
            float f = u - floorf(u);
            po[e] = (f < 0.5f) ? 1.f : 0.f;
            // queue near-boundary elements (both families: f~0.5 and f~0/1)
            float dist = fminf(fabsf(f - 0.5f), fminf(f, 1.0f - f));
            if (dist < EPS_F) {
                int pos = atomicAdd(&s_qcnt, 1);
                if (pos < QCAP) s_queue[pos] = (n << 8) | (mq * 4 + e);
            }
        }
        *(float4*)&out[((size_t)img * COUT + n) * LL + l0] = o;
    }
    __syncthreads();

    // =============== epilogue pass 2: thread-per-element exact fp32 rescue ===============
    // serial fp32 chain in ascending k order (cc -> ii -> jj): rounding correlates
    // with the reference accumulation (empirically fewest flips; R9/R11-proven)
    {
        const int nq = min(s_qcnt, QCAP);
        for (int q = t; q < nq; q += THREADS) {
            const int ent = s_queue[q];
            const int n   = ent >> 8;
            const int ml  = ent & 255;
            const int gm  = bm + ml;
            const int img = gm / LL;
            const int l   = gm - img * LL;
            const int y   = l / HWD;
            const int xq  = l - y * HWD;
            const float* xb = x + (size_t)img * (CIN * LL) + y * HWD + xq - (HWD + 1);
            const float* wr = Wg + (size_t)n * DD;

            float zacc = 0.f;
            for (int cc = 0; cc < CIN; cc++) {
                #pragma unroll
                for (int ii = 0; ii < 3; ii++)
                    #pragma unroll
                    for (int jj = 0; jj < 3; jj++) {
                        bool ok = ((unsigned)(y + ii - 1) < HWD) &&
                                  ((unsigned)(xq + jj - 1) < HWD);
                        float xv = ok ? __ldg(xb + cc * LL + ii * HWD + jj) : 0.f;
                        zacc = fmaf(xv, __ldg(wr + cc * 9 + ii * 3 + jj), zacc);
                    }
            }
            float u = fmaf(zacc, INV_PI, s_ub[n]);
            float f = u - floorf(u);
            out[((size_t)img * COUT + n) * LL + l] = (f < 0.5f) ? 1.f : 0.f;
        }
    }
}

extern "C" void kernel_launch(void* const* d_in, const int* in_sizes, int n_in,
                              void* d_out, int out_size) {
    const float* x = (const float*)d_in[0];   // (32, 64, 56, 56)
    const float* W = (const float*)d_in[1];   // (128, 576)
    const float* b = (const float*)d_in[2];   // (128,)
    float* out = (float*)d_out;               // (32, 128, 56, 56)

    cudaFuncSetAttribute(conv_mma_kernel,
                         cudaFuncAttributeMaxDynamicSharedMemorySize, SMEM_DYN);

    split_w_kernel<<<(COUT * DD + 255) / 256, 256>>>(W);
    conv_mma_kernel<<<MM / BM, THREADS, SMEM_DYN>>>(x, W, b, out);
}

// round 15
// speedup vs baseline: 1.9880x; 1.0005x over previous
#include <cuda_runtime.h>
#include <cuda_bf16.h>
#include <stdint.h>
#include <math.h>

// Problem constants
#define CIN    64
#define HWD    56
#define LL     3136
#define COUT   128
#define MM     100352
#define DD     576
#define BM     64
#define BK     64
#define NCHUNK 9
#define NSTAGE 2
#define THREADS 256          // warps 0-3 consumers, 4-7 producers
#define INV_PI 0.3183098861837907f
#define EPS_F  4e-4f
#define QCAP   512

// 2-way bf16 split of W, [COUT][DD]
__device__ __nv_bfloat16 g_Wh[COUT*DD];
__device__ __nv_bfloat16 g_Wm[COUT*DD];

__global__ void split_w_kernel(const float* __restrict__ W) {
    int i = blockIdx.x * 256 + threadIdx.x;
    if (i < COUT * DD) {
        float v = W[i];
        __nv_bfloat16 h = __float2bfloat16(v);
        float r1 = v - __bfloat162float(h);
        g_Wh[i] = h;
        g_Wm[i] = __float2bfloat16(r1);
    }
}

// ---------------- PTX helpers ----------------
__device__ __forceinline__ uint32_t smem_u32(const void* p) {
    uint32_t a;
    asm("{ .reg .u64 t; cvta.to.shared.u64 t, %1; cvt.u32.u64 %0, t; }" : "=r"(a) : "l"(p));
    return a;
}
#define MBAR_INIT(a, n) asm volatile("mbarrier.init.shared.b64 [%0], %1;" :: "r"(a), "r"(n) : "memory")
#define MBAR_ARRIVE(a)  asm volatile("mbarrier.arrive.shared.b64 _, [%0];" :: "r"(a) : "memory")
#define MBAR_WAIT(a, ph) do { \
    uint32_t _m = (a); uint32_t _p = (ph); uint32_t _d; \
    asm volatile("{\n\t.reg .pred p;\n\t" \
        "mbarrier.try_wait.parity.acquire.cta.shared::cta.b64 p, [%1], %2;\n\t" \
        "selp.b32 %0, 1, 0, p;\n\t}" : "=r"(_d) : "r"(_m), "r"(_p) : "memory"); \
    if (!_d) { \
        asm volatile("{\n\t.reg .pred P1;\n\t" \
            "WL_%=:\n\t" \
            "mbarrier.try_wait.parity.acquire.cta.shared::cta.b64 P1, [%0], %1, 0x989680;\n\t" \
            "@P1 bra.uni WD_%=;\n\t" \
            "bra.uni WL_%=;\n\t" \
            "WD_%=:\n\t}" :: "r"(_m), "r"(_p) : "memory"); \
    } } while (0)

#define STS128(a, v) asm volatile("st.shared.v4.b32 [%0], {%1,%2,%3,%4};" \
    :: "r"(a), "r"((v).x), "r"((v).y), "r"((v).z), "r"((v).w) : "memory")

#define CPASYNC16(dst, src) asm volatile( \
    "cp.async.cg.shared.global [%0], [%1], 16;" :: "r"(dst), "l"(src) : "memory")
#define CPASYNC_COMMIT() asm volatile("cp.async.commit_group;" ::: "memory")
#define CPASYNC_WAIT0()  asm volatile("cp.async.wait_group 0;" ::: "memory")

#define LDSM4(r, a) asm volatile( \
    "ldmatrix.sync.aligned.m8n8.x4.shared.b16 {%0,%1,%2,%3}, [%4];" \
    : "=r"((r)[0]), "=r"((r)[1]), "=r"((r)[2]), "=r"((r)[3]) : "r"(a))

#define MMA(cc, a, b0_, b1_) asm volatile( \
    "mma.sync.aligned.m16n8k16.row.col.f32.bf16.bf16.f32 " \
    "{%0,%1,%2,%3},{%4,%5,%6,%7},{%8,%9},{%0,%1,%2,%3};" \
    : "+f"((cc)[0]), "+f"((cc)[1]), "+f"((cc)[2]), "+f"((cc)[3]) \
    : "r"((a)[0]), "r"((a)[1]), "r"((a)[2]), "r"((a)[3]), "r"(b0_), "r"(b1_))

// one split-term over all 16 chains (2 mf x 4 g x 2 n8)
#define TERM(A_, B_) do { \
    _Pragma("unroll") \
    for (int mf_ = 0; mf_ < 2; mf_++) { \
        _Pragma("unroll") \
        for (int g_ = 0; g_ < 4; g_++) { \
            MMA(acc[mf_][g_ * 2 + 0], A_[mf_], B_[g_][0], B_[g_][1]); \
            MMA(acc[mf_][g_ * 2 + 1], A_[mf_], B_[g_][2], B_[g_][3]); \
        } \
    } } while (0)

// stage layout: Ah(8K) Am(8K) Bh(16K) Bm(16K) = 48KB per stage, 2 stages = 96KB
#define TILE_A  8192
#define TILE_BB 16384
#define AH_OFF  0
#define AM_OFF  8192
#define BH_OFF  16384
#define BM_OFF  32768
#define STAGE_B 49152
#define SMEM_DYN (NSTAGE * STAGE_B)

__global__ __launch_bounds__(THREADS, 2)
void conv_mma_kernel(const float* __restrict__ x,
                     const float* __restrict__ Wg,
                     const float* __restrict__ bias,
                     float* __restrict__ out) {
    extern __shared__ char dsm[];
    __shared__ __align__(8) unsigned long long s_bar[2 * NSTAGE];
    __shared__ int   s_tab[DD];
    __shared__ float s_ub[COUT];
    __shared__ int   s_qcnt;
    __shared__ int   s_queue[QCAP];

    const uint32_t sbase = smem_u32(dsm);
    uint32_t bar_full[NSTAGE], bar_empty[NSTAGE];
    #pragma unroll
    for (int s = 0; s < NSTAGE; s++) {
        bar_full[s]  = smem_u32(&s_bar[s]);
        bar_empty[s] = smem_u32(&s_bar[NSTAGE + s]);
    }

    const int t   = threadIdx.x;
    const int wid = t >> 5;
    const int lid = t & 31;
    const int bm  = blockIdx.x * BM;

    for (int k = t; k < DD; k += THREADS) {
        int c = k / 9, r = k - 9 * c;
        int i = r / 3, j = r - 3 * i;
        s_tab[k] = ((c * LL + i * HWD + j) << 4) | r;
    }
    if (t < COUT) s_ub[t] = fmaf(__ldg(&bias[t]), INV_PI, -0.25f);
    if (t == 0) {
        #pragma unroll
        for (int s = 0; s < NSTAGE; s++) {
            MBAR_INIT(bar_full[s], 128);    // 128 producer threads
            MBAR_INIT(bar_empty[s], 128);   // 128 consumer threads
        }
        s_qcnt = 0;
    }
    __syncthreads();

    // consumer accumulators: warp tile 32m x 64n; acc[mf(16m)][8 n8][4]
    float acc[2][8][4];
    const int wm = wid & 1;       // m offset 32*wm
    const int wn = wid >> 1;      // n offset 64*wn (valid for wid<4)

    if (wid >= 4) {
        // =============== producers (128 threads, 4 warps) ===============
        const int ptt  = t - 128;          // 0..127
        const int pr   = ptt & 63;         // A row within tile
        const int kh   = (ptt >> 6) * 32;  // A k-half: 0 or 32
        const int pbr  = ptt;              // B row 0..127
        const int gm   = bm + pr;
        const int img  = gm / LL;
        const int l    = gm - img * LL;
        const int y    = l / HWD;
        const int xx   = l - y * HWD;
        const float* xp = x + (long)img * (CIN * LL) + y * HWD + xx - (HWD + 1);

        uint32_t vmask = 0;
        #pragma unroll
        for (int i = 0; i < 3; i++)
            #pragma unroll
            for (int j = 0; j < 3; j++)
                if (((unsigned)(y + i - 1) < HWD) && ((unsigned)(xx + j - 1) < HWD))
                    vmask |= 1u << (i * 3 + j);

        const uint32_t swa   = (uint32_t)((pr & 7) << 4);
        const uint32_t swb   = (uint32_t)((pbr & 7) << 4);
        const long     wrowB = (long)pbr * DD;

        for (int c = 0; c < NCHUNK; c++) {
            const int s = c & 1;
            const int u = c >> 1;
            MBAR_WAIT(bar_empty[s], 1u ^ (u & 1));

            const uint32_t sb   = sbase + s * STAGE_B;
            const int kc = c * BK;

            // ---- B: async copy of pre-split weights (row pbr, 64 k) ----
            {
                const uint32_t brh = sb + BH_OFF + pbr * 128;
                const uint32_t brm = sb + BM_OFF + pbr * 128;
                const __nv_bfloat16* sH = g_Wh + wrowB + kc;
                const __nv_bfloat16* sM = g_Wm + wrowB + kc;
                #pragma unroll
                for (int q = 0; q < 8; q++) {
                    uint32_t off = ((uint32_t)(q * 16)) ^ swb;
                    CPASYNC16(brh + off, sH + q * 8);
                    CPASYNC16(brm + off, sM + q * 8);
                }
                CPASYNC_COMMIT();
            }

            // ---- A: im2col gather + 2-way bf16 split (row pr, 32 k) ----
            const uint32_t arow = sb + pr * 128;
            #pragma unroll
            for (int g = 0; g < 4; g++) {
                uint32_t ph[4], pmv[4];
                #pragma unroll
                for (int p = 0; p < 4; p++) {
                    int k  = kc + kh + g * 8 + p * 2;
                    int e0 = s_tab[k], e1 = s_tab[k + 1];
                    float v0 = ((vmask >> (e0 & 15)) & 1) ? __ldg(xp + (e0 >> 4)) : 0.f;
                    float v1 = ((vmask >> (e1 & 15)) & 1) ? __ldg(xp + (e1 >> 4)) : 0.f;
                    __nv_bfloat162 h2 = __floats2bfloat162_rn(v0, v1);
                    float r0 = v0 - __bfloat162float(h2.x);
                    float r1 = v1 - __bfloat162float(h2.y);
                    __nv_bfloat162 m2 = __floats2bfloat162_rn(r0, r1);
                    ph[p]  = *(uint32_t*)&h2;
                    pmv[p] = *(uint32_t*)&m2;
                }
                uint32_t off = ((uint32_t)(kh * 2 + g * 16)) ^ swa;
                uint4 vh = make_uint4(ph[0], ph[1], ph[2], ph[3]);
                uint4 vm = make_uint4(pmv[0], pmv[1], pmv[2], pmv[3]);
                STS128(arow + AH_OFF + off, vh);
                STS128(arow + AM_OFF + off, vm);
            }

            CPASYNC_WAIT0();
            MBAR_ARRIVE(bar_full[s]);
        }
    } else {
        // =============== consumers (128 threads, 4 warps) ===============
        #pragma unroll
        for (int i = 0; i < 2; i++)
            #pragma unroll
            for (int j = 0; j < 8; j++)
                #pragma unroll
                for (int e = 0; e < 4; e++) acc[i][j][e] = 0.f;

        const int rA = lid & 15;
        const int kAl = (lid >> 4) * 16;
        const uint32_t swA = (uint32_t)((rA & 7) << 4);
        const uint32_t byA = (uint32_t)(rA * 128);
        const int rB = (lid & 7) + ((lid >> 4) << 3);
        const int kBl = ((lid >> 3) & 1) * 16;
        const uint32_t swB = (uint32_t)((lid & 7) << 4);
        const uint32_t byB = (uint32_t)(rB * 128);

        const uint32_t mbase = (uint32_t)(wm * 32 * 128);
        const uint32_t nbase = (uint32_t)(wn * 64 * 128);

        for (int c = 0; c < NCHUNK; c++) {
            const int s = c & 1;
            const int u = c >> 1;
            MBAR_WAIT(bar_full[s], (u & 1));

            const uint32_t sb  = sbase + s * STAGE_B;
            const uint32_t pAh = sb + AH_OFF + mbase + byA;
            const uint32_t pAm = sb + AM_OFF + mbase + byA;
            const uint32_t pBh = sb + BH_OFF + nbase + byB;
            const uint32_t pBm = sb + BM_OFF + nbase + byB;

            #pragma unroll
            for (int ks = 0; ks < 4; ks++) {
                const uint32_t aoff = (uint32_t)((ks * 32 + kAl)) ^ swA;
                const uint32_t boff = (uint32_t)((ks * 32 + kBl)) ^ swB;

                uint32_t Bh[4][4], Bm[4][4];
                #pragma unroll
                for (int g = 0; g < 4; g++) {
                    const uint32_t go = (uint32_t)(g * (16 * 128));
                    LDSM4(Bh[g], pBh + go + boff);
                    LDSM4(Bm[g], pBm + go + boff);
                }
                uint32_t Ah[2][4], Am[2][4];
                #pragma unroll
                for (int mf = 0; mf < 2; mf++) {
                    const uint32_t ro = (uint32_t)(mf * (16 * 128));
                    LDSM4(Ah[mf], pAh + ro + aoff);
                    LDSM4(Am[mf], pAm + ro + aoff);
                }

                // 3 terms, direct accumulation (rescue covers dropped mm + RZ)
                TERM(Am, Bh);   // mh
                TERM(Ah, Bm);   // hm
                TERM(Ah, Bh);   // hh
            }
            MBAR_ARRIVE(bar_empty[s]);
        }
    }

    __syncthreads();

    // =============== epilogue pass 1: transpose + binarize + queue ===============
    float* scratch = (float*)dsm;          // [128 n][68 m] fp32 (34.8KB, reuses stages)
    if (wid < 4) {
        #pragma unroll
        for (int mf = 0; mf < 2; mf++) {
            const int m = wm * 32 + mf * 16 + (lid >> 2);
            #pragma unroll
            for (int nf = 0; nf < 8; nf++) {
                const int n = wn * 64 + nf * 8 + 2 * (lid & 3);
                scratch[n * 68 + m]           = acc[mf][nf][0];
                scratch[(n + 1) * 68 + m]     = acc[mf][nf][1];
                scratch[n * 68 + m + 8]       = acc[mf][nf][2];
                scratch[(n + 1) * 68 + m + 8] = acc[mf][nf][3];
            }
        }
    }
    __syncthreads();

    for (int i = t; i < COUT * 16; i += THREADS) {
        const int n  = i >> 4;
        const int mq = i & 15;
        float4 v = *(const float4*)&scratch[n * 68 + mq * 4];
        const int gm  = bm + mq * 4;
        const int img = gm / LL;
        const int l0  = gm - img * LL;
        const float ub = s_ub[n];
        float zs[4] = {v.x, v.y, v.z, v.w};
        float4 o;
        float* po = (float*)&o;
        #pragma unroll
        for (int e = 0; e < 4; e++) {
            float u = fmaf(zs[e], INV_PI, ub);
            float f = u - floorf(u);
            po[e] = (f < 0.5f) ? 1.f : 0.f;
            float dist = fminf(fabsf(f - 0.5f), fminf(f, 1.0f - f));
            if (dist < EPS_F) {
                int pos = atomicAdd(&s_qcnt, 1);
                if (pos < QCAP) s_queue[pos] = (n << 8) | (mq * 4 + e);
            }
        }
        *(float4*)&out[((size_t)img * COUT + n) * LL + l0] = o;
    }
    __syncthreads();

    // =============== epilogue pass 2: thread-per-element serial fp32 rescue ===============
    {
        const int nq = min(s_qcnt, QCAP);
        for (int q = t; q < nq; q += THREADS) {
            const int ent = s_queue[q];
            const int n   = ent >> 8;
            const int ml  = ent & 255;
            const int gm  = bm + ml;
            const int img = gm / LL;
            const int l   = gm - img * LL;
            const int y   = l / HWD;
            const int xq  = l - y * HWD;
            const float* xb = x + (size_t)img * (CIN * LL) + y * HWD + xq - (HWD + 1);
            const float* wr = Wg + (size_t)n * DD;

            float zacc = 0.f;
            for (int cc = 0; cc < CIN; cc++) {
                #pragma unroll
                for (int ii = 0; ii < 3; ii++)
                    #pragma unroll
                    for (int jj = 0; jj < 3; jj++) {
                        bool ok = ((unsigned)(y + ii - 1) < HWD) &&
                                  ((unsigned)(xq + jj - 1) < HWD);
                        float xv = ok ? __ldg(xb + cc * LL + ii * HWD + jj) : 0.f;
                        zacc = fmaf(xv, __ldg(wr + cc * 9 + ii * 3 + jj), zacc);
                    }
            }
            float u = fmaf(zacc, INV_PI, s_ub[n]);
            float f = u - floorf(u);
            out[((size_t)img * COUT + n) * LL + l] = (f < 0.5f) ? 1.f : 0.f;
        }
    }
}

extern "C" void kernel_launch(void* const* d_in, const int* in_sizes, int n_in,
                              void* d_out, int out_size) {
    const float* x = (const float*)d_in[0];   // (32, 64, 56, 56)
    const float* W = (const float*)d_in[1];   // (128, 576)
    const float* b = (const float*)d_in[2];   // (128,)
    float* out = (float*)d_out;               // (32, 128, 56, 56)

    cudaFuncSetAttribute(conv_mma_kernel,
                         cudaFuncAttributeMaxDynamicSharedMemorySize, SMEM_DYN);

    split_w_kernel<<<(COUT * DD + 255) / 256, 256>>>(W);
    conv_mma_kernel<<<MM / BM, THREADS, SMEM_DYN>>>(x, W, b, out);
}